// round 16
// baseline (speedup 1.0000x reference)
#include <cuda_runtime.h>
#include <cuda_bf16.h>
#include <cstdint>

#define B_   64
#define T_   512
#define E_   512
#define H_   1024
#define G3   3072
#define NCTA 128      // gru CTAs: (batch-half, unit-group-of-16)

// Single extern shared symbol for the whole TU.
extern __shared__ unsigned char smem_raw[];

// ---------------------------------------------------------------------------
// Device scratch (zero-initialized at load; no runtime allocation)
// ---------------------------------------------------------------------------
__device__ float g_xproj[(size_t)B_ * T_ * G3];              // input projections
__device__ __align__(128) unsigned g_hf[2][32768];           // ping-pong h, A-fragment order
__device__ __align__(16) unsigned g_abf[8388608];            // input as bf16 (32MB)
__device__ __align__(16) unsigned g_wbf[786432];             // W_ih as bf16 (3MB)
__device__ float    g_acc[B_];                               // head partials
__device__ unsigned g_ready[16];                             // [bh][chunk] version counters
__device__ unsigned g_cnt;                                   // barrier counter
__device__ unsigned g_gen;                                   // barrier generation

// ---------------------------------------------------------------------------
// Helpers
// ---------------------------------------------------------------------------
__device__ __forceinline__ void mma_bf16(float* c, unsigned a0, unsigned a1,
                                         unsigned a2, unsigned a3,
                                         unsigned b0, unsigned b1) {
    asm volatile(
        "mma.sync.aligned.m16n8k16.row.col.f32.bf16.bf16.f32 "
        "{%0,%1,%2,%3}, {%4,%5,%6,%7}, {%8,%9}, {%0,%1,%2,%3};\n"
        : "+f"(c[0]), "+f"(c[1]), "+f"(c[2]), "+f"(c[3])
        : "r"(a0), "r"(a1), "r"(a2), "r"(a3), "r"(b0), "r"(b1));
}

__device__ __forceinline__ float sigf(float x) {
    return 1.0f / (1.0f + __expf(-x));
}

__device__ __forceinline__ unsigned bf2u(float a, float b) {
    __nv_bfloat162 p = __floats2bfloat162_rn(a, b);
    return *reinterpret_cast<unsigned*>(&p);
}

// Grid barrier (init + final only): acq/rel atomics, no membar.gl.
__device__ __forceinline__ void grid_sync_dev() {
    __syncthreads();
    if (threadIdx.x == 0) {
        unsigned my;
        asm volatile("ld.acquire.gpu.global.u32 %0, [%1];"
                     : "=r"(my) : "l"(&g_gen));
        unsigned a;
        asm volatile("atom.acq_rel.gpu.global.add.u32 %0, [%1], 1;"
                     : "=r"(a) : "l"(&g_cnt));
        if (a == NCTA - 1) {
            asm volatile("st.relaxed.gpu.global.u32 [%0], 0;" :: "l"(&g_cnt));
            asm volatile("red.release.gpu.global.add.u32 [%0], 1;" :: "l"(&g_gen));
        } else {
            unsigned cur;
            do {
                asm volatile("ld.acquire.gpu.global.u32 %0, [%1];"
                             : "=r"(cur) : "l"(&g_gen));
            } while (cur == my);
        }
    }
    __syncthreads();
}

// ---------------------------------------------------------------------------
// Phase 0: convert input + W_ih to bf16 (bit-identical rounding to in-loop cvt)
// ---------------------------------------------------------------------------
__global__ void __launch_bounds__(256)
prep_kernel(const float* __restrict__ A, const float* __restrict__ W)
{
    const size_t stride = (size_t)gridDim.x * blockDim.x;
    const size_t tid0   = (size_t)blockIdx.x * blockDim.x + threadIdx.x;
    for (size_t i = tid0; i < 4194304; i += stride) {
        float4 v = *(const float4*)(A + i * 4);
        uint2 o; o.x = bf2u(v.x, v.y); o.y = bf2u(v.z, v.w);
        *(uint2*)&g_abf[i * 2] = o;
    }
    for (size_t i = tid0; i < 393216; i += stride) {
        float4 v = *(const float4*)(W + i * 4);
        uint2 o; o.x = bf2u(v.x, v.y); o.y = bf2u(v.z, v.w);
        *(uint2*)&g_wbf[i * 2] = o;
    }
}

// ---------------------------------------------------------------------------
// Phase 1: x_proj = input @ W_ih^T + b_ih  (bf16 mma; operands pre-bf16, so
// staging is plain 16B LDG->STS copies; same fragment format as R14,
// row stride 28 u32 = 112B (16B-aligned, conflict-free).
// ---------------------------------------------------------------------------
#define XS_STRIDE 28   // u32 per row (16 data + 12 pad); 112B, 16B-aligned

__global__ void __launch_bounds__(256)
xproj_kernel(const float* __restrict__ bih, const int* __restrict__ seqlen)
{
    const int tm = blockIdx.y, tn = blockIdx.x;
    const int b  = (tm << 7) >> 9;
    const int t0 = (tm << 7) & 511;
    if (t0 >= seqlen[b]) return;

    unsigned* As = (unsigned*)smem_raw;                 // [2][128][28]
    unsigned* Bs = As + 2 * 128 * XS_STRIDE;            // [2][128][28]

    const int tid  = threadIdx.x;
    const int lane = tid & 31, wid = tid >> 5;
    const int warpM = wid >> 2, warpN = wid & 3;
    const int tc = lane & 3, tr = lane >> 2;

    // thread's staging chunks: f = tid + i*256 in [0,512): row r=f>>2, 16B j=f&3
    const char* Agb = (const char*)g_abf + (size_t)(tm * 128) * 1024;  // bf16 row=1024B
    const char* Bgb = (const char*)g_wbf + (size_t)(tn * 128) * 1024;

    float acc[4][4][4];
#pragma unroll
    for (int i = 0; i < 4; i++)
#pragma unroll
        for (int j = 0; j < 4; j++)
#pragma unroll
            for (int k = 0; k < 4; k++) acc[i][j][k] = 0.0f;

    // stage ko=0 into buffer 0
#pragma unroll
    for (int i = 0; i < 2; i++) {
        int f = tid + i * 256;
        int r = f >> 2, j = f & 3;
        uint4 va = *(const uint4*)(Agb + r * 1024 + j * 16);
        uint4 vb = *(const uint4*)(Bgb + r * 1024 + j * 16);
        *(uint4*)&As[r * XS_STRIDE + j * 4] = va;
        *(uint4*)&Bs[r * XS_STRIDE + j * 4] = vb;
    }
    __syncthreads();

    for (int ko = 0; ko < 16; ko++) {
        uint4 pa[2], pb[2];
        if (ko < 15) {
            int kb = (ko + 1) * 64;     // byte offset along K (32 bf16 = 64B)
#pragma unroll
            for (int i = 0; i < 2; i++) {
                int f = tid + i * 256;
                int r = f >> 2, j = f & 3;
                pa[i] = *(const uint4*)(Agb + r * 1024 + kb + j * 16);
                pb[i] = *(const uint4*)(Bgb + r * 1024 + kb + j * 16);
            }
        }
        const unsigned* Ab = As + (ko & 1) * 128 * XS_STRIDE;
        const unsigned* Bb = Bs + (ko & 1) * 128 * XS_STRIDE;
#pragma unroll
        for (int kk2 = 0; kk2 < 2; kk2++) {
            const int base = kk2 * 8 + tc;
            unsigned a[4][4];
#pragma unroll
            for (int mt = 0; mt < 4; mt++) {
                int r = warpM * 64 + mt * 16 + tr;
                a[mt][0] = Ab[r * XS_STRIDE + base];
                a[mt][1] = Ab[(r + 8) * XS_STRIDE + base];
                a[mt][2] = Ab[r * XS_STRIDE + base + 4];
                a[mt][3] = Ab[(r + 8) * XS_STRIDE + base + 4];
            }
#pragma unroll
            for (int nt = 0; nt < 4; nt++) {
                int n = warpN * 32 + nt * 8 + tr;
                unsigned b0 = Bb[n * XS_STRIDE + base];
                unsigned b1 = Bb[n * XS_STRIDE + base + 4];
#pragma unroll
                for (int mt = 0; mt < 4; mt++)
                    mma_bf16(acc[mt][nt], a[mt][0], a[mt][1], a[mt][2], a[mt][3], b0, b1);
            }
        }
        if (ko < 15) {
            unsigned* Ad = As + ((ko + 1) & 1) * 128 * XS_STRIDE;
            unsigned* Bd = Bs + ((ko + 1) & 1) * 128 * XS_STRIDE;
#pragma unroll
            for (int i = 0; i < 2; i++) {
                int f = tid + i * 256;
                int r = f >> 2, j = f & 3;
                *(uint4*)&Ad[r * XS_STRIDE + j * 4] = pa[i];
                *(uint4*)&Bd[r * XS_STRIDE + j * 4] = pb[i];
            }
        }
        __syncthreads();
    }

#pragma unroll
    for (int nt = 0; nt < 4; nt++) {
        int cg = tn * 128 + warpN * 32 + nt * 8 + 2 * tc;
        float bv0 = bih[cg], bv1 = bih[cg + 1];
#pragma unroll
        for (int mt = 0; mt < 4; mt++) {
            int rg = tm * 128 + warpM * 64 + mt * 16 + tr;
            float2 v0 = make_float2(acc[mt][nt][0] + bv0, acc[mt][nt][1] + bv1);
            float2 v1 = make_float2(acc[mt][nt][2] + bv0, acc[mt][nt][3] + bv1);
            *(float2*)&g_xproj[(size_t)rg * G3 + cg]       = v0;
            *(float2*)&g_xproj[(size_t)(rg + 8) * G3 + cg] = v1;
        }
    }
}

// ---------------------------------------------------------------------------
// Phase 2: persistent GRU (R14 verbatim + Tmax early exit).
// 128 CTAs x 256 thr. CTA c = (bh = c&1 batch-half-of-32, g = c>>1 unit
// group-of-16). Each CTA reads only its batch-half of h (8MB/step chip-wide).
// Warp q = kt-chunk-of-8: 96 mma, 16 LDG.128, W-frags 96 u32 in regs.
// Sync: g_ready[bh*8+chunk], 8 producers each, single-address acquire poll.
// ---------------------------------------------------------------------------
#define SMEM2 (8 * 32 * 52 * 4 + 64)
#define HPS   52       // hpq row stride (floats): 48 data + 4 pad

__global__ void __launch_bounds__(256, 1)
gru_kernel(const int* __restrict__ seqlen, const float* __restrict__ W_hh,
           const float* __restrict__ b_hh, const float* __restrict__ W_out,
           const float* __restrict__ b_out, float* __restrict__ out)
{
    float* hpq = (float*)smem_raw;              // [8][32][HPS] partial C

    const int c    = blockIdx.x;
    const int bh   = c & 1;                      // batch half
    const int g    = c >> 1;                     // unit group 0..63
    const int tid  = threadIdx.x;
    const int lane = tid & 31, wid = tid >> 5;
    const int q    = wid;                        // kt chunk 0..7 (8 kt each)
    const int tc = lane & 3, tr = lane >> 2;
    const int mych = bh * 8 + (g >> 3);          // counter this CTA bumps

    // ---- reset ready counters (replay safety) -------------------------------
    if (c == 0 && tid < 16)
        asm volatile("st.relaxed.gpu.global.u32 [%0], 0;" :: "l"(&g_ready[tid]));

    // ---- Tmax = max(seqlen) (uniform across grid) ---------------------------
    if (tid == 0) {
        int mx = 0;
        for (int j = 0; j < B_; j++) mx = max(mx, seqlen[j]);
        ((int*)hpq)[0] = mx;
    }
    __syncthreads();
    const int Tmax = ((int*)hpq)[0];
    __syncthreads();

    // ---- load W_hh B-fragments into registers (kt = q*8 + kt2) --------------
    unsigned wb0[8][6], wb1[8][6];
#pragma unroll
    for (int nt = 0; nt < 6; nt++) {
        int o = nt * 8 + tr;
        const float* wr = W_hh + (size_t)((o >> 4) * H_ + g * 16 + (o & 15)) * H_;
#pragma unroll
        for (int kt2 = 0; kt2 < 8; kt2++) {
            int k0 = (q * 8 + kt2) * 16 + tc * 2;
            wb0[kt2][nt] = bf2u(wr[k0],     wr[k0 + 1]);
            wb1[kt2][nt] = bf2u(wr[k0 + 8], wr[k0 + 9]);
        }
    }

    // ---- pointwise identity: local batch lb (of my half), 2 units ub2 -------
    const int lb     = tid >> 3;                 // 0..31
    const int ub2    = (tid & 7) << 1;           // 0,2,..,14
    const int b_mine = bh * 32 + lb;             // global batch
    const int sl     = seqlen[b_mine];
    float bhs[3][2];
#pragma unroll
    for (int gg = 0; gg < 3; gg++) {
        bhs[gg][0] = b_hh[gg * H_ + g * 16 + ub2];
        bhs[gg][1] = b_hh[gg * H_ + g * 16 + ub2 + 1];
    }
    float hv[2] = {0.f, 0.f};

    // fragment-slot offset (u32 units): kt block = g, row = b_mine, cols ub2
    const int r_b    = b_mine & 15;
    const int mt_b   = b_mine >> 4;              // 0..3
    const int lane_b = ((r_b & 7) << 2) | ((ub2 & 7) >> 1);
    const int reg_b  = ((ub2 & 8) ? 2 : 0) | (r_b >> 3);
    const unsigned fo = (((unsigned)(g * 4 + mt_b) * 32 + lane_b) << 2) + reg_b;

    // zero my slot of frag buffer 0 (h version 0); zero head accumulators
    {
        unsigned* p = &g_hf[0][fo];
        asm volatile("st.global.cg.u32 [%0], 0;" :: "l"(p));
    }
    if (c == 0 && tid < B_) g_acc[tid] = 0.f;

    // orders: counter resets + version-0 stores across the grid
    grid_sync_dev();

    // announce version 0
    if (tid == 0)
        asm volatile("red.release.gpu.global.add.u32 [%0], 1;"
                     :: "l"(&g_ready[mych]));

    // per-thread A-operand base (u32): (kt*4 + bh*2 + mtl)*128 + lane*4
    const unsigned aoff = (unsigned)(q * 4096 + bh * 256 + lane * 4);
    unsigned* const mycnt = &g_ready[bh * 8 + q];

    for (int t = 0; t < Tmax; t++) {
        const int rb = t & 1, wb = rb ^ 1;

        // ---- xproj loads (DRAM, independent of h) ---------------------------
        const bool active = t < sl;
        float2 xr, xz, xn;
        if (active) {
            size_t base = ((size_t)b_mine * T_ + t) * G3 + g * 16 + ub2;
            xr = __ldcg((const float2*)&g_xproj[base]);
            xz = __ldcg((const float2*)&g_xproj[base + H_]);
            xn = __ldcg((const float2*)&g_xproj[base + 2 * H_]);
        }

        // ---- all lanes: acquire-poll my half's chunk-q counter ---------------
        {
            const unsigned target = 8u * (unsigned)(t + 1);
            unsigned v;
            do {
                asm volatile("ld.acquire.gpu.global.u32 %0, [%1];"
                             : "=r"(v) : "l"(mycnt));
            } while (v < target);
        }

        const unsigned* hb = &g_hf[rb][0] + aoff;

        float acc[2][6][4];
#pragma unroll
        for (int mtl = 0; mtl < 2; mtl++)
#pragma unroll
            for (int nt = 0; nt < 6; nt++)
#pragma unroll
                for (int j = 0; j < 4; j++) acc[mtl][nt][j] = 0.f;

        // ---- direct-from-L2 mma loop, depth-2 prefetch ring -------------------
        unsigned af[2][2][4];
#pragma unroll
        for (int mtl = 0; mtl < 2; mtl++)
            asm volatile("ld.global.cg.v4.u32 {%0,%1,%2,%3}, [%4];"
                         : "=r"(af[0][mtl][0]), "=r"(af[0][mtl][1]),
                           "=r"(af[0][mtl][2]), "=r"(af[0][mtl][3])
                         : "l"(hb + mtl * 128));
#pragma unroll
        for (int kt2 = 0; kt2 < 8; kt2++) {
            const int cur = kt2 & 1, nxt = cur ^ 1;
            if (kt2 < 7) {
#pragma unroll
                for (int mtl = 0; mtl < 2; mtl++)
                    asm volatile("ld.global.cg.v4.u32 {%0,%1,%2,%3}, [%4];"
                                 : "=r"(af[nxt][mtl][0]), "=r"(af[nxt][mtl][1]),
                                   "=r"(af[nxt][mtl][2]), "=r"(af[nxt][mtl][3])
                                 : "l"(hb + (kt2 + 1) * 512 + mtl * 128));
            }
#pragma unroll
            for (int mtl = 0; mtl < 2; mtl++)
#pragma unroll
                for (int nt = 0; nt < 6; nt++)
                    mma_bf16(acc[mtl][nt], af[cur][mtl][0], af[cur][mtl][1],
                             af[cur][mtl][2], af[cur][mtl][3],
                             wb0[kt2][nt], wb1[kt2][nt]);
        }

        // ---- dump partials to hpq[q][row][col] -------------------------------
        {
            float* hq = hpq + q * (32 * HPS);
            int col = (tc << 1);
#pragma unroll
            for (int mtl = 0; mtl < 2; mtl++) {
                int row = mtl * 16 + tr;
#pragma unroll
                for (int nt = 0; nt < 6; nt++) {
                    int cc = col + nt * 8;
                    *(float2*)&hq[row * HPS + cc] =
                        make_float2(acc[mtl][nt][0], acc[mtl][nt][1]);
                    *(float2*)&hq[(row + 8) * HPS + cc] =
                        make_float2(acc[mtl][nt][2], acc[mtl][nt][3]);
                }
            }
        }
        __syncthreads();   // gates h-store on ALL warps' polls

        // ---- pointwise GRU update (fp32 carry), summing 8 q-partials ---------
        if (active) {
            float hr0 = 0.f, hr1 = 0.f, hz0 = 0.f, hz1 = 0.f, hn0 = 0.f, hn1 = 0.f;
            const int rowoff = lb * HPS;
#pragma unroll
            for (int qq = 0; qq < 8; qq++) {
                const float* hq = hpq + qq * (32 * HPS) + rowoff;
                float2 vr = *(const float2*)&hq[ub2];
                float2 vz = *(const float2*)&hq[16 + ub2];
                float2 vn = *(const float2*)&hq[32 + ub2];
                hr0 += vr.x; hr1 += vr.y;
                hz0 += vz.x; hz1 += vz.y;
                hn0 += vn.x; hn1 += vn.y;
            }
            {
                float r = sigf(xr.x + hr0 + bhs[0][0]);
                float z = sigf(xz.x + hz0 + bhs[1][0]);
                float n = tanhf(xn.x + r * (hn0 + bhs[2][0]));
                hv[0] = (1.0f - z) * n + z * hv[0];
            }
            {
                float r = sigf(xr.y + hr1 + bhs[0][1]);
                float z = sigf(xz.y + hz1 + bhs[1][1]);
                float n = tanhf(xn.y + r * (hn1 + bhs[2][1]));
                hv[1] = (1.0f - z) * n + z * hv[1];
            }
        }
        // write h version t+1 (bf16x2, fragment order)
        {
            unsigned u0 = bf2u(hv[0], hv[1]);
            unsigned* p = &g_hf[wb][fo];
            asm volatile("st.global.cg.u32 [%0], %1;" :: "l"(p), "r"(u0));
        }
        __syncthreads();   // all h stores issued before announce

        // announce version t+1
        if (tid == 0)
            asm volatile("red.release.gpu.global.add.u32 [%0], 1;"
                         :: "l"(&g_ready[mych]));
    }

    // ---- head: out[b] = sigmoid(h[b] . W_out + b_out) ------------------------
    float part = hv[0] * W_out[g * 16 + ub2] + hv[1] * W_out[g * 16 + ub2 + 1];
    part += __shfl_down_sync(0xffffffffu, part, 1);
    part += __shfl_down_sync(0xffffffffu, part, 2);
    part += __shfl_down_sync(0xffffffffu, part, 4);
    if ((tid & 7) == 0) atomicAdd(&g_acc[b_mine], part);

    grid_sync_dev();

    if (c == 0 && tid < B_) {
        float v = __ldcg(&g_acc[tid]);
        out[tid] = 1.0f / (1.0f + expf(-(v + b_out[0])));
    }
}

// ---------------------------------------------------------------------------
// Launch
// ---------------------------------------------------------------------------
extern "C" void kernel_launch(void* const* d_in, const int* in_sizes, int n_in,
                              void* d_out, int out_size)
{
    const float* input  = (const float*)d_in[0];
    const int*   seqlen = (const int*)  d_in[1];
    const float* W_ih   = (const float*)d_in[2];
    const float* W_hh   = (const float*)d_in[3];
    const float* b_ih   = (const float*)d_in[4];
    const float* b_hh   = (const float*)d_in[5];
    const float* W_out  = (const float*)d_in[6];
    const float* b_out  = (const float*)d_in[7];
    float* out = (float*)d_out;

    const int SMEM1 = 2 * 2 * 128 * XS_STRIDE * (int)sizeof(unsigned);  // 57344 B

    cudaFuncSetAttribute(xproj_kernel, cudaFuncAttributeMaxDynamicSharedMemorySize, SMEM1);
    cudaFuncSetAttribute(gru_kernel,   cudaFuncAttributeMaxDynamicSharedMemorySize, SMEM2);

    prep_kernel<<<512, 256>>>(input, W_ih);
    xproj_kernel<<<dim3(24, 256), 256, SMEM1>>>(b_ih, seqlen);
    gru_kernel<<<NCTA, 256, SMEM2>>>(seqlen, W_hh, b_hh, W_out, b_out, out);
}

// round 17
// speedup vs baseline: 1.4415x; 1.4415x over previous
#include <cuda_runtime.h>
#include <cuda_bf16.h>
#include <cstdint>

#define B_   64
#define T_   512
#define E_   512
#define H_   1024
#define G3   3072
#define NCTA 128      // gru CTAs: (batch-half, unit-group-of-16)

// Single extern shared symbol for the whole TU.
extern __shared__ unsigned char smem_raw[];

// ---------------------------------------------------------------------------
// Device scratch (zero-initialized at load; no runtime allocation)
// ---------------------------------------------------------------------------
__device__ float g_xproj[(size_t)B_ * T_ * G3];              // input projections
__device__ __align__(128) unsigned g_hf[2][32768];           // ping-pong h, A-fragment order
__device__ float    g_acc[B_];                               // head partials
__device__ unsigned g_ready[16];                             // [bh][chunk] version counters
__device__ unsigned g_cnt;                                   // barrier counter
__device__ unsigned g_gen;                                   // barrier generation

// ---------------------------------------------------------------------------
// Helpers
// ---------------------------------------------------------------------------
__device__ __forceinline__ void mma_bf16(float* c, unsigned a0, unsigned a1,
                                         unsigned a2, unsigned a3,
                                         unsigned b0, unsigned b1) {
    asm volatile(
        "mma.sync.aligned.m16n8k16.row.col.f32.bf16.bf16.f32 "
        "{%0,%1,%2,%3}, {%4,%5,%6,%7}, {%8,%9}, {%0,%1,%2,%3};\n"
        : "+f"(c[0]), "+f"(c[1]), "+f"(c[2]), "+f"(c[3])
        : "r"(a0), "r"(a1), "r"(a2), "r"(a3), "r"(b0), "r"(b1));
}

__device__ __forceinline__ float sigf(float x) {
    return 1.0f / (1.0f + __expf(-x));
}

__device__ __forceinline__ unsigned bf2u(float a, float b) {
    __nv_bfloat162 p = __floats2bfloat162_rn(a, b);
    return *reinterpret_cast<unsigned*>(&p);
}

// Grid barrier (init + final only): acq/rel atomics, no membar.gl.
__device__ __forceinline__ void grid_sync_dev() {
    __syncthreads();
    if (threadIdx.x == 0) {
        unsigned my;
        asm volatile("ld.acquire.gpu.global.u32 %0, [%1];"
                     : "=r"(my) : "l"(&g_gen));
        unsigned a;
        asm volatile("atom.acq_rel.gpu.global.add.u32 %0, [%1], 1;"
                     : "=r"(a) : "l"(&g_cnt));
        if (a == NCTA - 1) {
            asm volatile("st.relaxed.gpu.global.u32 [%0], 0;" :: "l"(&g_cnt));
            asm volatile("red.release.gpu.global.add.u32 [%0], 1;" :: "l"(&g_gen));
        } else {
            unsigned cur;
            do {
                asm volatile("ld.acquire.gpu.global.u32 %0, [%1];"
                             : "=r"(cur) : "l"(&g_gen));
            } while (cur == my);
        }
    }
    __syncthreads();
}

// ---------------------------------------------------------------------------
// Phase 1: x_proj = input @ W_ih^T + b_ih  (bf16 mma, R14 version, unchanged)
// ---------------------------------------------------------------------------
#define XS_STRIDE 20   // u32 per row (16 data + 4 pad)

__global__ void __launch_bounds__(256)
xproj_kernel(const float* __restrict__ A, const float* __restrict__ W,
             const float* __restrict__ bih, const int* __restrict__ seqlen)
{
    const int tm = blockIdx.y, tn = blockIdx.x;
    const int b  = (tm << 7) >> 9;
    const int t0 = (tm << 7) & 511;
    if (t0 >= seqlen[b]) return;

    unsigned* As = (unsigned*)smem_raw;                 // [2][128][20]
    unsigned* Bs = As + 2 * 128 * XS_STRIDE;            // [2][128][20]

    const int tid  = threadIdx.x;
    const int lane = tid & 31, wid = tid >> 5;
    const int warpM = wid >> 2, warpN = wid & 3;
    const int tc = lane & 3, tr = lane >> 2;

    const float* Ag = A + (size_t)(tm * 128) * E_;
    const float* Bg = W + (size_t)(tn * 128) * E_;

    float acc[4][4][4];
#pragma unroll
    for (int i = 0; i < 4; i++)
#pragma unroll
        for (int j = 0; j < 4; j++)
#pragma unroll
            for (int k = 0; k < 4; k++) acc[i][j][k] = 0.0f;

#pragma unroll
    for (int i = 0; i < 4; i++) {
        int f = tid + i * 256;
        int r = f >> 3, c4 = (f & 7) << 2;
        float4 va = *(const float4*)(Ag + (size_t)r * E_ + c4);
        float4 vb = *(const float4*)(Bg + (size_t)r * E_ + c4);
        As[r * XS_STRIDE + (c4 >> 1)]     = bf2u(va.x, va.y);
        As[r * XS_STRIDE + (c4 >> 1) + 1] = bf2u(va.z, va.w);
        Bs[r * XS_STRIDE + (c4 >> 1)]     = bf2u(vb.x, vb.y);
        Bs[r * XS_STRIDE + (c4 >> 1) + 1] = bf2u(vb.z, vb.w);
    }
    __syncthreads();

    for (int ko = 0; ko < 16; ko++) {
        float4 pa[4], pb[4];
        if (ko < 15) {
            int kb = (ko + 1) * 32;
#pragma unroll
            for (int i = 0; i < 4; i++) {
                int f = tid + i * 256;
                int r = f >> 3, c4 = (f & 7) << 2;
                pa[i] = *(const float4*)(Ag + (size_t)r * E_ + kb + c4);
                pb[i] = *(const float4*)(Bg + (size_t)r * E_ + kb + c4);
            }
        }
        const unsigned* Ab = As + (ko & 1) * 128 * XS_STRIDE;
        const unsigned* Bb = Bs + (ko & 1) * 128 * XS_STRIDE;
#pragma unroll
        for (int kk2 = 0; kk2 < 2; kk2++) {
            const int base = kk2 * 8 + tc;
            unsigned a[4][4];
#pragma unroll
            for (int mt = 0; mt < 4; mt++) {
                int r = warpM * 64 + mt * 16 + tr;
                a[mt][0] = Ab[r * XS_STRIDE + base];
                a[mt][1] = Ab[(r + 8) * XS_STRIDE + base];
                a[mt][2] = Ab[r * XS_STRIDE + base + 4];
                a[mt][3] = Ab[(r + 8) * XS_STRIDE + base + 4];
            }
#pragma unroll
            for (int nt = 0; nt < 4; nt++) {
                int n = warpN * 32 + nt * 8 + tr;
                unsigned b0 = Bb[n * XS_STRIDE + base];
                unsigned b1 = Bb[n * XS_STRIDE + base + 4];
#pragma unroll
                for (int mt = 0; mt < 4; mt++)
                    mma_bf16(acc[mt][nt], a[mt][0], a[mt][1], a[mt][2], a[mt][3], b0, b1);
            }
        }
        if (ko < 15) {
            unsigned* Ad = As + ((ko + 1) & 1) * 128 * XS_STRIDE;
            unsigned* Bd = Bs + ((ko + 1) & 1) * 128 * XS_STRIDE;
#pragma unroll
            for (int i = 0; i < 4; i++) {
                int f = tid + i * 256;
                int r = f >> 3, c4 = (f & 7) << 2;
                Ad[r * XS_STRIDE + (c4 >> 1)]     = bf2u(pa[i].x, pa[i].y);
                Ad[r * XS_STRIDE + (c4 >> 1) + 1] = bf2u(pa[i].z, pa[i].w);
                Bd[r * XS_STRIDE + (c4 >> 1)]     = bf2u(pb[i].x, pb[i].y);
                Bd[r * XS_STRIDE + (c4 >> 1) + 1] = bf2u(pb[i].z, pb[i].w);
            }
        }
        __syncthreads();
    }

#pragma unroll
    for (int nt = 0; nt < 4; nt++) {
        int cg = tn * 128 + warpN * 32 + nt * 8 + 2 * tc;
        float bv0 = bih[cg], bv1 = bih[cg + 1];
#pragma unroll
        for (int mt = 0; mt < 4; mt++) {
            int rg = tm * 128 + warpM * 64 + mt * 16 + tr;
            float2 v0 = make_float2(acc[mt][nt][0] + bv0, acc[mt][nt][1] + bv1);
            float2 v1 = make_float2(acc[mt][nt][2] + bv0, acc[mt][nt][3] + bv1);
            *(float2*)&g_xproj[(size_t)rg * G3 + cg]       = v0;
            *(float2*)&g_xproj[(size_t)(rg + 8) * G3 + cg] = v1;
        }
    }
}

// ---------------------------------------------------------------------------
// Phase 2: persistent GRU (R14 verbatim + Tmax early exit).
// 128 CTAs x 256 thr. CTA c = (bh = c&1 batch-half-of-32, g = c>>1 unit
// group-of-16). Each CTA reads only its batch-half of h (8MB/step chip-wide).
// Warp q = kt-chunk-of-8: 96 mma, 16 LDG.128, W-frags 96 u32 in regs.
// Sync: g_ready[bh*8+chunk], 8 producers each, single-address acquire poll.
// ---------------------------------------------------------------------------
#define SMEM2 (8 * 32 * 52 * 4 + 64)
#define HPS   52       // hpq row stride (floats): 48 data + 4 pad

__global__ void __launch_bounds__(256, 1)
gru_kernel(const int* __restrict__ seqlen, const float* __restrict__ W_hh,
           const float* __restrict__ b_hh, const float* __restrict__ W_out,
           const float* __restrict__ b_out, float* __restrict__ out)
{
    float* hpq = (float*)smem_raw;              // [8][32][HPS] partial C

    const int c    = blockIdx.x;
    const int bh   = c & 1;                      // batch half
    const int g    = c >> 1;                     // unit group 0..63
    const int tid  = threadIdx.x;
    const int lane = tid & 31, wid = tid >> 5;
    const int q    = wid;                        // kt chunk 0..7 (8 kt each)
    const int tc = lane & 3, tr = lane >> 2;
    const int mych = bh * 8 + (g >> 3);          // counter this CTA bumps

    // ---- reset ready counters (replay safety) -------------------------------
    if (c == 0 && tid < 16)
        asm volatile("st.relaxed.gpu.global.u32 [%0], 0;" :: "l"(&g_ready[tid]));

    // ---- Tmax = max(seqlen): uniform across grid, computed per-warp ---------
    int Tmax = 0;
    {
        int v = (lane < 16) ? seqlen[lane * 4 + 0] : 0;
        int v1 = (lane < 16) ? seqlen[lane * 4 + 1] : 0;
        int v2 = (lane < 16) ? seqlen[lane * 4 + 2] : 0;
        int v3 = (lane < 16) ? seqlen[lane * 4 + 3] : 0;
        v = max(max(v, v1), max(v2, v3));
#pragma unroll
        for (int off = 16; off > 0; off >>= 1)
            v = max(v, __shfl_xor_sync(0xffffffffu, v, off));
        Tmax = v;
    }

    // ---- load W_hh B-fragments into registers (kt = q*8 + kt2) --------------
    unsigned wb0[8][6], wb1[8][6];
#pragma unroll
    for (int nt = 0; nt < 6; nt++) {
        int o = nt * 8 + tr;
        const float* wr = W_hh + (size_t)((o >> 4) * H_ + g * 16 + (o & 15)) * H_;
#pragma unroll
        for (int kt2 = 0; kt2 < 8; kt2++) {
            int k0 = (q * 8 + kt2) * 16 + tc * 2;
            wb0[kt2][nt] = bf2u(wr[k0],     wr[k0 + 1]);
            wb1[kt2][nt] = bf2u(wr[k0 + 8], wr[k0 + 9]);
        }
    }

    // ---- pointwise identity: local batch lb (of my half), 2 units ub2 -------
    const int lb     = tid >> 3;                 // 0..31
    const int ub2    = (tid & 7) << 1;           // 0,2,..,14
    const int b_mine = bh * 32 + lb;             // global batch
    const int sl     = seqlen[b_mine];
    float bhs[3][2];
#pragma unroll
    for (int gg = 0; gg < 3; gg++) {
        bhs[gg][0] = b_hh[gg * H_ + g * 16 + ub2];
        bhs[gg][1] = b_hh[gg * H_ + g * 16 + ub2 + 1];
    }
    float hv[2] = {0.f, 0.f};

    // fragment-slot offset (u32 units): kt block = g, row = b_mine, cols ub2
    const int r_b    = b_mine & 15;
    const int mt_b   = b_mine >> 4;              // 0..3
    const int lane_b = ((r_b & 7) << 2) | ((ub2 & 7) >> 1);
    const int reg_b  = ((ub2 & 8) ? 2 : 0) | (r_b >> 3);
    const unsigned fo = (((unsigned)(g * 4 + mt_b) * 32 + lane_b) << 2) + reg_b;

    // zero my slot of frag buffer 0 (h version 0); zero head accumulators
    {
        unsigned* p = &g_hf[0][fo];
        asm volatile("st.global.cg.u32 [%0], 0;" :: "l"(p));
    }
    if (c == 0 && tid < B_) g_acc[tid] = 0.f;

    // orders: counter resets + version-0 stores across the grid
    grid_sync_dev();

    // announce version 0
    if (tid == 0)
        asm volatile("red.release.gpu.global.add.u32 [%0], 1;"
                     :: "l"(&g_ready[mych]));

    // per-thread A-operand base (u32): (kt*4 + bh*2 + mtl)*128 + lane*4
    const unsigned aoff = (unsigned)(q * 4096 + bh * 256 + lane * 4);
    unsigned* const mycnt = &g_ready[bh * 8 + q];

    for (int t = 0; t < Tmax; t++) {
        const int rb = t & 1, wb = rb ^ 1;

        // ---- xproj loads (DRAM, independent of h) ---------------------------
        const bool active = t < sl;
        float2 xr, xz, xn;
        if (active) {
            size_t base = ((size_t)b_mine * T_ + t) * G3 + g * 16 + ub2;
            xr = __ldcg((const float2*)&g_xproj[base]);
            xz = __ldcg((const float2*)&g_xproj[base + H_]);
            xn = __ldcg((const float2*)&g_xproj[base + 2 * H_]);
        }

        // ---- all lanes: acquire-poll my half's chunk-q counter ---------------
        {
            const unsigned target = 8u * (unsigned)(t + 1);
            unsigned v;
            do {
                asm volatile("ld.acquire.gpu.global.u32 %0, [%1];"
                             : "=r"(v) : "l"(mycnt));
            } while (v < target);
        }

        const unsigned* hb = &g_hf[rb][0] + aoff;

        float acc[2][6][4];
#pragma unroll
        for (int mtl = 0; mtl < 2; mtl++)
#pragma unroll
            for (int nt = 0; nt < 6; nt++)
#pragma unroll
                for (int j = 0; j < 4; j++) acc[mtl][nt][j] = 0.f;

        // ---- direct-from-L2 mma loop, depth-2 prefetch ring -------------------
        unsigned af[2][2][4];
#pragma unroll
        for (int mtl = 0; mtl < 2; mtl++)
            asm volatile("ld.global.cg.v4.u32 {%0,%1,%2,%3}, [%4];"
                         : "=r"(af[0][mtl][0]), "=r"(af[0][mtl][1]),
                           "=r"(af[0][mtl][2]), "=r"(af[0][mtl][3])
                         : "l"(hb + mtl * 128));
#pragma unroll
        for (int kt2 = 0; kt2 < 8; kt2++) {
            const int cur = kt2 & 1, nxt = cur ^ 1;
            if (kt2 < 7) {
#pragma unroll
                for (int mtl = 0; mtl < 2; mtl++)
                    asm volatile("ld.global.cg.v4.u32 {%0,%1,%2,%3}, [%4];"
                                 : "=r"(af[nxt][mtl][0]), "=r"(af[nxt][mtl][1]),
                                   "=r"(af[nxt][mtl][2]), "=r"(af[nxt][mtl][3])
                                 : "l"(hb + (kt2 + 1) * 512 + mtl * 128));
            }
#pragma unroll
            for (int mtl = 0; mtl < 2; mtl++)
#pragma unroll
                for (int nt = 0; nt < 6; nt++)
                    mma_bf16(acc[mtl][nt], af[cur][mtl][0], af[cur][mtl][1],
                             af[cur][mtl][2], af[cur][mtl][3],
                             wb0[kt2][nt], wb1[kt2][nt]);
        }

        // ---- dump partials to hpq[q][row][col] -------------------------------
        {
            float* hq = hpq + q * (32 * HPS);
            int col = (tc << 1);
#pragma unroll
            for (int mtl = 0; mtl < 2; mtl++) {
                int row = mtl * 16 + tr;
#pragma unroll
                for (int nt = 0; nt < 6; nt++) {
                    int cc = col + nt * 8;
                    *(float2*)&hq[row * HPS + cc] =
                        make_float2(acc[mtl][nt][0], acc[mtl][nt][1]);
                    *(float2*)&hq[(row + 8) * HPS + cc] =
                        make_float2(acc[mtl][nt][2], acc[mtl][nt][3]);
                }
            }
        }
        __syncthreads();   // gates h-store on ALL warps' polls

        // ---- pointwise GRU update (fp32 carry), summing 8 q-partials ---------
        if (active) {
            float hr0 = 0.f, hr1 = 0.f, hz0 = 0.f, hz1 = 0.f, hn0 = 0.f, hn1 = 0.f;
            const int rowoff = lb * HPS;
#pragma unroll
            for (int qq = 0; qq < 8; qq++) {
                const float* hq = hpq + qq * (32 * HPS) + rowoff;
                float2 vr = *(const float2*)&hq[ub2];
                float2 vz = *(const float2*)&hq[16 + ub2];
                float2 vn = *(const float2*)&hq[32 + ub2];
                hr0 += vr.x; hr1 += vr.y;
                hz0 += vz.x; hz1 += vz.y;
                hn0 += vn.x; hn1 += vn.y;
            }
            {
                float r = sigf(xr.x + hr0 + bhs[0][0]);
                float z = sigf(xz.x + hz0 + bhs[1][0]);
                float n = tanhf(xn.x + r * (hn0 + bhs[2][0]));
                hv[0] = (1.0f - z) * n + z * hv[0];
            }
            {
                float r = sigf(xr.y + hr1 + bhs[0][1]);
                float z = sigf(xz.y + hz1 + bhs[1][1]);
                float n = tanhf(xn.y + r * (hn1 + bhs[2][1]));
                hv[1] = (1.0f - z) * n + z * hv[1];
            }
        }
        // write h version t+1 (bf16x2, fragment order)
        {
            unsigned u0 = bf2u(hv[0], hv[1]);
            unsigned* p = &g_hf[wb][fo];
            asm volatile("st.global.cg.u32 [%0], %1;" :: "l"(p), "r"(u0));
        }
        __syncthreads();   // all h stores issued before announce

        // announce version t+1
        if (tid == 0)
            asm volatile("red.release.gpu.global.add.u32 [%0], 1;"
                         :: "l"(&g_ready[mych]));
    }

    // ---- head: out[b] = sigmoid(h[b] . W_out + b_out) ------------------------
    float part = hv[0] * W_out[g * 16 + ub2] + hv[1] * W_out[g * 16 + ub2 + 1];
    part += __shfl_down_sync(0xffffffffu, part, 1);
    part += __shfl_down_sync(0xffffffffu, part, 2);
    part += __shfl_down_sync(0xffffffffu, part, 4);
    if ((tid & 7) == 0) atomicAdd(&g_acc[b_mine], part);

    grid_sync_dev();

    if (c == 0 && tid < B_) {
        float v = __ldcg(&g_acc[tid]);
        out[tid] = 1.0f / (1.0f + expf(-(v + b_out[0])));
    }
}

// ---------------------------------------------------------------------------
// Launch
// ---------------------------------------------------------------------------
extern "C" void kernel_launch(void* const* d_in, const int* in_sizes, int n_in,
                              void* d_out, int out_size)
{
    const float* input  = (const float*)d_in[0];
    const int*   seqlen = (const int*)  d_in[1];
    const float* W_ih   = (const float*)d_in[2];
    const float* W_hh   = (const float*)d_in[3];
    const float* b_ih   = (const float*)d_in[4];
    const float* b_hh   = (const float*)d_in[5];
    const float* W_out  = (const float*)d_in[6];
    const float* b_out  = (const float*)d_in[7];
    float* out = (float*)d_out;

    const int SMEM1 = 2 * 2 * 128 * XS_STRIDE * (int)sizeof(unsigned);  // 40960 B

    cudaFuncSetAttribute(xproj_kernel, cudaFuncAttributeMaxDynamicSharedMemorySize, SMEM1);
    cudaFuncSetAttribute(gru_kernel,   cudaFuncAttributeMaxDynamicSharedMemorySize, SMEM2);

    xproj_kernel<<<dim3(24, 256), 256, SMEM1>>>(input, W_ih, b_ih, seqlen);
    gru_kernel<<<NCTA, 256, SMEM2>>>(seqlen, W_hh, b_hh, W_out, b_out, out);
}